// round 11
// baseline (speedup 1.0000x reference)
#include <cuda_runtime.h>
#include <cuda_fp16.h>
#include <cstdint>
#include <math.h>

#define Bn 2
#define Ln 2048
#define Dn 512
#define Vn 50257
#define NLn 12
#define Kn 5
#define An 128
#define Hn 128
#define BLn (Bn*Ln)
#define BLD (Bn*Ln*Dn)

#define SROW 36                                   /* u32 per smem row */
#define NSTG 3
#define GEMM_SMEM  (NSTG * 2 * 128 * SROW * 4)    /* 110,592 B */
#define LOGIT_SMEM (NSTG * (128 + 256) * SROW * 4)/* 165,888 B */
#define DUAL_SMEM  (2 * 3 * 128 * SROW * 4)       /* 110,592 B */
#define EGRID (BLD / 256)                         /* 8192 */

// ---------------- scratch (device globals) -----------------------------------
__device__ __align__(16) float  g_x[BLD];
__device__ __align__(16) float  g_xn[BLD];
__device__ __align__(16) float  g_y[BLD];
__device__ __align__(16) float  g_xs[Bn*Ln*An];
__device__ __align__(16) __half g_t1h[BLD];
__device__ __align__(16) __half g_yh[BLD];
__device__ __align__(16) __half g_hdnh[Bn*Ln*Hn];
__device__ __align__(16) __half g_xnh[BLD];
__device__ __align__(16) __half g_embh[Vn*Dn];
__device__ __align__(16) __half g_pwh [NLn*Dn*Dn];
__device__ __align__(16) __half g_w1h [NLn*Dn*Dn];
__device__ __align__(16) __half g_w2h [NLn*Dn*Dn];
__device__ __align__(16) __half g_dnh [NLn*Hn*Dn];
__device__ __align__(16) __half g_uph [NLn*Dn*Hn];

// ---------------- fp32 -> fp16 -----------------------------------------------
__global__ void f2h_k(const float* __restrict__ src, __half* __restrict__ dst,
                      int n4) {
    int i = blockIdx.x * blockDim.x + threadIdx.x;
    if (i >= n4) return;
    float4 v = ((const float4*)src)[i];
    ((__half2*)dst)[i * 2]     = __floats2half2_rn(v.x, v.y);
    ((__half2*)dst)[i * 2 + 1] = __floats2half2_rn(v.z, v.w);
}

// ---------------- embedding + rope ------------------------------------------
__global__ void embed_rope_k(const int* __restrict__ tok,
                             const float* __restrict__ emb,
                             float* __restrict__ x) {
    int idx = blockIdx.x * blockDim.x + threadIdx.x;
    if (idx >= BLD) return;
    int d  = idx & (Dn - 1);
    int bl = idx >> 9;
    int l  = bl & (Ln - 1);
    int t  = tok[bl];
    const float* e = emb + (size_t)t * Dn;
    const int half = Dn / 2;
    int fi = (d < half) ? d : d - half;
    float invf = powf(10000.f, -(float)fi / (float)half);
    float ang  = (float)l * invf;
    float s, c;
    sincosf(ang, &s, &c);
    float v = e[d];
    float partner = (d < half) ? -e[d + half] : e[d - half];
    x[idx] = v * c + partner * s;
}

// ---------------- rmsnorm ----------------------------------------------------
__global__ void rmsnorm_k(const float* __restrict__ x,
                          const float* __restrict__ w,
                          float* __restrict__ o,
                          __half* __restrict__ oh) {
    int row = blockIdx.x;
    int t = threadIdx.x;
    const float* xr = x + (size_t)row * Dn;
    float a  = xr[t];
    float b2 = xr[t + 256];
    __shared__ float red[256];
    red[t] = a * a + b2 * b2;
    __syncthreads();
    for (int s = 128; s > 0; s >>= 1) {
        if (t < s) red[t] += red[t + s];
        __syncthreads();
    }
    float scale = rsqrtf(red[0] / (float)Dn + 1e-6f);
    float v0 = w[t] * a * scale;
    float v1 = w[t + 256] * b2 * scale;
    if (o) {
        o[(size_t)row * Dn + t]       = v0;
        o[(size_t)row * Dn + t + 256] = v1;
    }
    if (oh) {
        oh[(size_t)row * Dn + t]       = __float2half_rn(v0);
        oh[(size_t)row * Dn + t + 256] = __float2half_rn(v1);
    }
}

// ---------------- dconv + exact serial recurrence (fused launch) -------------
// blocks [0, EGRID): depthwise dilated conv -> t1h
// blocks [EGRID, EGRID+Bn): serial scan h = a*h + b*x  -> xs  (exact ref order)
__global__ void dconv_recur_k(const float* __restrict__ xn,
                              const float* __restrict__ dw,
                              const float* __restrict__ db,
                              const float* __restrict__ alpha,
                              const float* __restrict__ beta,
                              __half* __restrict__ t1h,
                              float* __restrict__ xs,
                              int dil) {
    int bid = blockIdx.x;
    if (bid < EGRID) {
        int idx = bid * 256 + threadIdx.x;
        int d  = idx & (Dn - 1);
        int bl = idx >> 9;
        int l  = bl & (Ln - 1);
        int b  = bl >> 11;
        float s = db[d];
#pragma unroll
        for (int k = 0; k < Kn; k++) {
            int t = l + (k - 2) * dil;
            if (t >= 0 && t < Ln)
                s += dw[d * Kn + k] * xn[(((size_t)(b * Ln + t)) << 9) + d];
        }
        t1h[idx] = __float2half_rn(s);
    } else if (threadIdx.x < An) {
        int b = bid - EGRID;
        int a = threadIdx.x;
        float al = alpha[a], be = beta[a];
        const float* xp = xn + ((size_t)(b * Ln) << 9) + a;
        float* op = xs + (size_t)(b * Ln) * An + a;
        float h = 0.f;
#pragma unroll 8
        for (int l = 0; l < Ln; l++) {
            h = fmaf(al, h, be * xp[(size_t)l << 9]);
            op[(size_t)l * An] = h;
        }
    }
}

// ---------------- helpers ----------------------------------------------------
__device__ __forceinline__ void cp16(uint32_t dst, const void* src, bool pred) {
    asm volatile("cp.async.cg.shared.global [%0], [%1], 16, %2;\n"
                 :: "r"(dst), "l"(src), "r"(pred ? 16 : 0));
}
#define HMMA(acc, a, b)                                                        \
    asm volatile(                                                              \
        "mma.sync.aligned.m16n8k16.row.col.f32.f16.f16.f32 "                   \
        "{%0,%1,%2,%3}, {%4,%5,%6,%7}, {%8,%9}, {%0,%1,%2,%3};\n"              \
        : "+f"(acc[0]), "+f"(acc[1]), "+f"(acc[2]), "+f"(acc[3])               \
        : "r"(a[0]), "r"(a[1]), "r"(a[2]), "r"(a[3]), "r"(b[0]), "r"(b[1]))
#define LDSM4(r0, r1, r2, r3, addr)                                            \
    asm volatile("ldmatrix.sync.aligned.m8n8.x4.shared.b16 {%0,%1,%2,%3}, [%4];" \
                 : "=r"(r0), "=r"(r1), "=r"(r2), "=r"(r3) : "r"(addr))

// ---------------- fp16 GEMM, 128xBN tile, BK=64, 3-stage, 1 sync/iter --------
// EPI 0: C=v   EPI 1: gelu->Ch   EPI 2: C=C+add1+v
// EPI 3: C = v + (col<An ? add1[m*An+col] : aux[idx]);  Ch mirror
template <int EPI, int BN>
__global__ void __launch_bounds__(256, (BN == 128) ? 2 : 1)
gemm_h(const __half* __restrict__ A,
       const __half* __restrict__ Bw,
       const float* __restrict__ bias,
       const float* __restrict__ add1,
       const float* __restrict__ aux,
       float* __restrict__ C,
       __half* __restrict__ Ch,
       int M, int N, int K) {
    extern __shared__ uint32_t sm[];
    const uint32_t sbase = (uint32_t)__cvta_generic_to_shared(sm);
    const uint32_t bbase = sbase + NSTG * 128 * SROW * 4;
    constexpr int NT = BN / 32;                   // n-frags per warp

    const int tid  = threadIdx.x;
    const int m0   = blockIdx.y * 128;
    const int n0   = blockIdx.x * BN;
    const int wid  = tid >> 5;
    const int lane = tid & 31;
    const int gid  = lane >> 2;
    const int tig  = lane & 3;
    const int mb   = (wid >> 2) * 64;
    const int nb   = (wid & 3) * (BN / 4);

    const uint32_t aoff = (((uint32_t)(lane & 15)) * SROW + ((lane >> 4) & 1) * 4) * 4;
    const uint32_t boff = (((uint32_t)((lane & 7) + ((lane >> 4) & 1) * 8)) * SROW
                           + ((lane >> 3) & 1) * 4) * 4;

    float acc[4][NT][4];
#pragma unroll
    for (int mt = 0; mt < 4; mt++)
#pragma unroll
        for (int nt = 0; nt < NT; nt++)
#pragma unroll
            for (int r = 0; r < 4; r++) acc[mt][nt][r] = 0.f;

    const int KT = K >> 6;                        // BK=64

    auto issue = [&](int kt, int s) {
        int k0 = kt << 6;
#pragma unroll
        for (int j = 0; j < 4; j++) {             // A: 128 rows
            int cid = tid + j * 256;
            int r   = cid >> 3;
            int col = cid & 7;
            cp16(sbase + ((s * 128 + r) * SROW + col * 4) * 4,
                 A + (size_t)(m0 + r) * K + k0 + col * 8, true);
        }
#pragma unroll
        for (int j = 0; j < BN / 32; j++) {       // B: BN rows
            int cid = tid + j * 256;
            int r   = cid >> 3;
            int col = cid & 7;
            int nr  = n0 + r;
            cp16(bbase + ((s * BN + r) * SROW + col * 4) * 4,
                 Bw + (size_t)(nr < N ? nr : 0) * K + k0 + col * 8, nr < N);
        }
    };

#pragma unroll
    for (int p = 0; p < NSTG - 1; p++) {
        if (p < KT) issue(p, p);
        asm volatile("cp.async.commit_group;\n");
    }

    for (int kt = 0; kt < KT; kt++) {
        const int s = kt % NSTG;
        asm volatile("cp.async.wait_group %0;\n" :: "n"(NSTG - 2));
        __syncthreads();
        {   // prefetch into stage (kt-1)%NSTG — consumed last iter, all warps past barrier
            int kn = kt + NSTG - 1;
            if (kn < KT) issue(kn, kn % NSTG);
            asm volatile("cp.async.commit_group;\n");
        }

        const uint32_t as0 = sbase + (uint32_t)(s * 128 * SROW * 4) + aoff;
        const uint32_t bs0 = bbase + (uint32_t)(s * BN * SROW * 4) + boff;
#pragma unroll
        for (int k8 = 0; k8 < 4; k8++) {
            const uint32_t ko4 = (uint32_t)(k8 * 8) * 4;
            uint32_t a[4][4], b[NT][2];
#pragma unroll
            for (int mt = 0; mt < 4; mt++)
                LDSM4(a[mt][0], a[mt][1], a[mt][2], a[mt][3],
                      as0 + (uint32_t)((mb + mt * 16) * SROW * 4) + ko4);
#pragma unroll
            for (int p = 0; p < NT / 2; p++)
                LDSM4(b[2*p][0], b[2*p][1], b[2*p+1][0], b[2*p+1][1],
                      bs0 + (uint32_t)((nb + p * 16) * SROW * 4) + ko4);
#pragma unroll
            for (int mt = 0; mt < 4; mt++)
#pragma unroll
                for (int nt = 0; nt < NT; nt++)
                    HMMA(acc[mt][nt], a[mt], b[nt]);
        }
    }

#pragma unroll
    for (int mt = 0; mt < 4; mt++) {
        int row0 = m0 + mb + mt * 16 + gid;
#pragma unroll
        for (int nt = 0; nt < NT; nt++) {
            int col0 = n0 + nb + nt * 8 + tig * 2;
#pragma unroll
            for (int hf = 0; hf < 2; hf++) {
                int rr = row0 + hf * 8;
#pragma unroll
                for (int cc = 0; cc < 2; cc++) {
                    int col = col0 + cc;
                    if (col < N) {
                        float v = acc[mt][nt][hf * 2 + cc] + (bias ? bias[col] : 0.f);
                        size_t idx = (size_t)rr * N + col;
                        if (EPI == 0) {
                            C[idx] = v;
                        } else if (EPI == 1) {
                            float g = 0.5f * v * (1.f + erff(v * 0.70710678118654752f));
                            Ch[idx] = __float2half_rn(g);
                        } else if (EPI == 2) {
                            C[idx] = C[idx] + add1[idx] + v;
                        } else {
                            float r = (col < An) ? add1[(size_t)rr * An + col]
                                                 : aux[idx];
                            float o = v + r;
                            C[idx]  = o;
                            Ch[idx] = __float2half_rn(o);
                        }
                    }
                }
            }
        }
    }
}

// ---------------- fused w1|w2 GEMM + GLU (2-stage, proven) -------------------
__global__ void __launch_bounds__(256)
w1w2glu_k(const __half* __restrict__ Ah,
          const __half* __restrict__ W1,
          const __half* __restrict__ W2,
          const float* __restrict__ b1,
          const float* __restrict__ b2,
          float* __restrict__ y,
          __half* __restrict__ yh) {
    extern __shared__ uint32_t sm[];
    const uint32_t sbase  = (uint32_t)__cvta_generic_to_shared(sm);
    const uint32_t b1base = sbase + 2 * 128 * SROW * 4;
    const uint32_t b2base = sbase + 4 * 128 * SROW * 4;

    const int tid  = threadIdx.x;
    const int m0   = blockIdx.y * 128;
    const int n0   = blockIdx.x * 128;
    const int wid  = tid >> 5;
    const int lane = tid & 31;
    const int gid  = lane >> 2;
    const int tig  = lane & 3;
    const int mb   = (wid >> 2) * 64;
    const int nb   = (wid & 3) * 32;
    const int K    = Dn;

    const uint32_t aoff = (((uint32_t)(lane & 15)) * SROW + ((lane >> 4) & 1) * 4) * 4;
    const uint32_t boff = (((uint32_t)((lane & 7) + ((lane >> 4) & 1) * 8)) * SROW
                           + ((lane >> 3) & 1) * 4) * 4;

    float acc1[4][4][4], acc2[4][4][4];
#pragma unroll
    for (int mt = 0; mt < 4; mt++)
#pragma unroll
        for (int nt = 0; nt < 4; nt++)
#pragma unroll
            for (int r = 0; r < 4; r++) { acc1[mt][nt][r] = 0.f; acc2[mt][nt][r] = 0.f; }

    const int KT = K >> 6;

    auto issue = [&](int kt, int s) {
        int k0 = kt << 6;
#pragma unroll
        for (int j = 0; j < 4; j++) {
            int cid = tid + j * 256;
            int r   = cid >> 3;
            int col = cid & 7;
            uint32_t so = ((s * 128 + r) * SROW + col * 4) * 4;
            cp16(sbase  + so, Ah + (size_t)(m0 + r) * K + k0 + col * 8, true);
            cp16(b1base + so, W1 + (size_t)(n0 + r) * K + k0 + col * 8, true);
            cp16(b2base + so, W2 + (size_t)(n0 + r) * K + k0 + col * 8, true);
        }
    };

    issue(0, 0);
    asm volatile("cp.async.commit_group;\n");

    for (int kt = 0; kt < KT; kt++) {
        int s = kt & 1;
        if (kt + 1 < KT) {
            issue(kt + 1, s ^ 1);
            asm volatile("cp.async.commit_group;\n");
            asm volatile("cp.async.wait_group 1;\n");
        } else {
            asm volatile("cp.async.wait_group 0;\n");
        }
        __syncthreads();

        const uint32_t as0  = sbase  + (uint32_t)(s * 128 * SROW * 4) + aoff;
        const uint32_t b1s0 = b1base + (uint32_t)(s * 128 * SROW * 4) + boff;
        const uint32_t b2s0 = b2base + (uint32_t)(s * 128 * SROW * 4) + boff;
#pragma unroll
        for (int k8 = 0; k8 < 4; k8++) {
            const uint32_t ko4 = (uint32_t)(k8 * 8) * 4;
            uint32_t a[4][4], br1[4][2], br2[4][2];
#pragma unroll
            for (int mt = 0; mt < 4; mt++)
                LDSM4(a[mt][0], a[mt][1], a[mt][2], a[mt][3],
                      as0 + (uint32_t)((mb + mt * 16) * SROW * 4) + ko4);
#pragma unroll
            for (int p = 0; p < 2; p++) {
                LDSM4(br1[2*p][0], br1[2*p][1], br1[2*p+1][0], br1[2*p+1][1],
                      b1s0 + (uint32_t)((nb + p * 16) * SROW * 4) + ko4);
                LDSM4(br2[2*p][0], br2[2*p][1], br2[2*p+1][0], br2[2*p+1][1],
                      b2s0 + (uint32_t)((nb + p * 16) * SROW * 4) + ko4);
            }
#pragma unroll
            for (int mt = 0; mt < 4; mt++)
#pragma unroll
                for (int nt = 0; nt < 4; nt++) {
                    HMMA(acc1[mt][nt], a[mt], br1[nt]);
                    HMMA(acc2[mt][nt], a[mt], br2[nt]);
                }
        }
        __syncthreads();
    }

#pragma unroll
    for (int mt = 0; mt < 4; mt++) {
        int row0 = m0 + mb + mt * 16 + gid;
#pragma unroll
        for (int nt = 0; nt < 4; nt++) {
            int col0 = n0 + nb + nt * 8 + tig * 2;
#pragma unroll
            for (int hf = 0; hf < 2; hf++) {
                int rr = row0 + hf * 8;
#pragma unroll
                for (int cc = 0; cc < 2; cc++) {
                    int col = col0 + cc;
                    float v1 = acc1[mt][nt][hf * 2 + cc] + b1[col];
                    float v2 = acc2[mt][nt][hf * 2 + cc] + b2[col];
                    size_t idx = (size_t)rr * Dn + col;
                    float o = y[idx] + (1.f / (1.f + expf(-v1))) * tanhf(v2);
                    y[idx]  = o;
                    yh[idx] = __float2half_rn(o);
                }
            }
        }
    }
}

// ---------------- host ------------------------------------------------------
extern "C" void kernel_launch(void* const* d_in, const int* in_sizes, int n_in,
                              void* d_out, int out_size) {
    const int*   tokens  = (const int*)  d_in[0];
    const float* emb     = (const float*)d_in[1];
    const float* norm_w  = (const float*)d_in[2];
    const float* dconv_w = (const float*)d_in[3];
    const float* dconv_b = (const float*)d_in[4];
    const float* pconv_w = (const float*)d_in[5];
    const float* pconv_b = (const float*)d_in[6];
    const float* alpha   = (const float*)d_in[7];
    const float* beta    = (const float*)d_in[8];
    const float* w1      = (const float*)d_in[9];
    const float* b1      = (const float*)d_in[10];
    const float* w2      = (const float*)d_in[11];
    const float* b2      = (const float*)d_in[12];
    const float* down_w  = (const float*)d_in[13];
    const float* down_b  = (const float*)d_in[14];
    const float* up_w    = (const float*)d_in[15];
    const float* up_b    = (const float*)d_in[16];
    const float* fnw     = (const float*)d_in[17];
    float* out = (float*)d_out;

    float *x, *xn, *y, *xs;
    __half *t1h, *yh, *hdnh, *xnh, *embh, *pwh, *w1h, *w2h, *dnh, *uph;
    cudaGetSymbolAddress((void**)&x,    g_x);
    cudaGetSymbolAddress((void**)&xn,   g_xn);
    cudaGetSymbolAddress((void**)&y,    g_y);
    cudaGetSymbolAddress((void**)&xs,   g_xs);
    cudaGetSymbolAddress((void**)&t1h,  g_t1h);
    cudaGetSymbolAddress((void**)&yh,   g_yh);
    cudaGetSymbolAddress((void**)&hdnh, g_hdnh);
    cudaGetSymbolAddress((void**)&xnh,  g_xnh);
    cudaGetSymbolAddress((void**)&embh, g_embh);
    cudaGetSymbolAddress((void**)&pwh,  g_pwh);
    cudaGetSymbolAddress((void**)&w1h,  g_w1h);
    cudaGetSymbolAddress((void**)&w2h,  g_w2h);
    cudaGetSymbolAddress((void**)&dnh,  g_dnh);
    cudaGetSymbolAddress((void**)&uph,  g_uph);

    cudaFuncSetAttribute(gemm_h<1,128>, cudaFuncAttributeMaxDynamicSharedMemorySize, GEMM_SMEM);
    cudaFuncSetAttribute(gemm_h<2,128>, cudaFuncAttributeMaxDynamicSharedMemorySize, GEMM_SMEM);
    cudaFuncSetAttribute(gemm_h<3,128>, cudaFuncAttributeMaxDynamicSharedMemorySize, GEMM_SMEM);
    cudaFuncSetAttribute(gemm_h<0,256>, cudaFuncAttributeMaxDynamicSharedMemorySize, LOGIT_SMEM);
    cudaFuncSetAttribute(w1w2glu_k,     cudaFuncAttributeMaxDynamicSharedMemorySize, DUAL_SMEM);

    {
        int n;
        n = Vn * Dn / 4;        f2h_k<<<(n + 255) / 256, 256>>>(emb,     embh, n);
        n = NLn * Dn * Dn / 4;  f2h_k<<<(n + 255) / 256, 256>>>(pconv_w, pwh,  n);
        n = NLn * Dn * Dn / 4;  f2h_k<<<(n + 255) / 256, 256>>>(w1,      w1h,  n);
        n = NLn * Dn * Dn / 4;  f2h_k<<<(n + 255) / 256, 256>>>(w2,      w2h,  n);
        n = NLn * Hn * Dn / 4;  f2h_k<<<(n + 255) / 256, 256>>>(down_w,  dnh,  n);
        n = NLn * Dn * Hn / 4;  f2h_k<<<(n + 255) / 256, 256>>>(up_w,    uph,  n);
    }

    embed_rope_k<<<EGRID, 256>>>(tokens, emb, x);

    for (int i = 0; i < NLn; i++) {
        int dil = 1 << (i % 3);
        rmsnorm_k<<<BLn, 256>>>(x, norm_w + i * Dn, xn, nullptr);
        dconv_recur_k<<<EGRID + Bn, 256>>>(xn, dconv_w + (size_t)i * Dn * Kn,
                                           dconv_b + i * Dn,
                                           alpha + i * An, beta + i * An,
                                           t1h, xs, dil);

        dim3 gpw(Dn / 128, BLn / 128);  // (4, 32)
        gemm_h<3,128><<<gpw, 256, GEMM_SMEM>>>(
            t1h, pwh + (size_t)i * Dn * Dn, pconv_b + i * Dn,
            xs, xn, y, yh, BLn, Dn, Dn);

        w1w2glu_k<<<gpw, 256, DUAL_SMEM>>>(
            yh, w1h + (size_t)i * Dn * Dn, w2h + (size_t)i * Dn * Dn,
            b1 + i * Dn, b2 + i * Dn, y, yh);

        dim3 gdn(Hn / 128, BLn / 128);  // (1, 32)
        gemm_h<1,128><<<gdn, 256, GEMM_SMEM>>>(
            yh, dnh + (size_t)i * Hn * Dn, down_b + i * Hn,
            nullptr, nullptr, nullptr, hdnh, BLn, Hn, Dn);

        gemm_h<2,128><<<gpw, 256, GEMM_SMEM>>>(
            hdnh, uph + (size_t)i * Dn * Hn, up_b + i * Dn,
            y, nullptr, x, nullptr, BLn, Dn, Hn);
    }

    rmsnorm_k<<<BLn, 256>>>(x, fnw, nullptr, xnh);
    dim3 gl((Vn + 255) / 256, BLn / 128);  // (197, 32)
    gemm_h<0,256><<<gl, 256, LOGIT_SMEM>>>(
        xnh, embh, nullptr, nullptr, nullptr, out, nullptr, BLn, Vn, Dn);
}

// round 12
// speedup vs baseline: 1.2883x; 1.2883x over previous
#include <cuda_runtime.h>
#include <cuda_fp16.h>
#include <cstdint>
#include <math.h>

#define Bn 2
#define Ln 2048
#define Dn 512
#define Vn 50257
#define NLn 12
#define Kn 5
#define An 128
#define Hn 128
#define BLn (Bn*Ln)
#define BLD (Bn*Ln*Dn)
#define CHK 128
#define CLEN 16

#define SROW 36                                   /* u32 per smem row */
#define GEMM_SMEM  (2 * 2 * 128 * SROW * 4)       /* 73,728 B  */
#define LOGIT_SMEM (2 * (128 + 256) * SROW * 4)   /* 110,592 B */
#define DUAL_SMEM  (2 * 3 * 128 * SROW * 4)       /* 110,592 B */

// ---------------- scratch (device globals) -----------------------------------
__device__ __align__(16) float  g_x[BLD];
__device__ __align__(16) float  g_xn[BLD];
__device__ __align__(16) float  g_y[BLD];
__device__ __align__(16) float  g_xs[Bn*Ln*An];
__device__ __align__(16) float  g_pc [Bn*CHK*An];
__device__ __align__(16) float  g_pcx[Bn*CHK*An];
__device__ __align__(16) __half g_t1h[BLD];
__device__ __align__(16) __half g_yh[BLD];
__device__ __align__(16) __half g_hdnh[Bn*Ln*Hn];
__device__ __align__(16) __half g_xnh[BLD];
__device__ __align__(16) __half g_embh[Vn*Dn];
__device__ __align__(16) __half g_pwh [NLn*Dn*Dn];
__device__ __align__(16) __half g_w1h [NLn*Dn*Dn];
__device__ __align__(16) __half g_w2h [NLn*Dn*Dn];
__device__ __align__(16) __half g_dnh [NLn*Hn*Dn];
__device__ __align__(16) __half g_uph [NLn*Dn*Hn];

// ---------------- fp32 -> fp16 -----------------------------------------------
__global__ void f2h_k(const float* __restrict__ src, __half* __restrict__ dst,
                      int n4) {
    int i = blockIdx.x * blockDim.x + threadIdx.x;
    if (i >= n4) return;
    float4 v = ((const float4*)src)[i];
    ((__half2*)dst)[i * 2]     = __floats2half2_rn(v.x, v.y);
    ((__half2*)dst)[i * 2 + 1] = __floats2half2_rn(v.z, v.w);
}

// ---------------- embedding + rope ------------------------------------------
__global__ void embed_rope_k(const int* __restrict__ tok,
                             const float* __restrict__ emb,
                             float* __restrict__ x) {
    int idx = blockIdx.x * blockDim.x + threadIdx.x;
    if (idx >= BLD) return;
    int d  = idx & (Dn - 1);
    int bl = idx >> 9;
    int l  = bl & (Ln - 1);
    int t  = tok[bl];
    const float* e = emb + (size_t)t * Dn;
    const int half = Dn / 2;
    int fi = (d < half) ? d : d - half;
    float invf = powf(10000.f, -(float)fi / (float)half);
    float ang  = (float)l * invf;
    float s, c;
    sincosf(ang, &s, &c);
    float v = e[d];
    float partner = (d < half) ? -e[d + half] : e[d - half];
    x[idx] = v * c + partner * s;
}

// ---------------- rmsnorm ----------------------------------------------------
__global__ void rmsnorm_k(const float* __restrict__ x,
                          const float* __restrict__ w,
                          float* __restrict__ o,
                          __half* __restrict__ oh) {
    int row = blockIdx.x;
    int t = threadIdx.x;
    const float* xr = x + (size_t)row * Dn;
    float a  = xr[t];
    float b2 = xr[t + 256];
    __shared__ float red[256];
    red[t] = a * a + b2 * b2;
    __syncthreads();
    for (int s = 128; s > 0; s >>= 1) {
        if (t < s) red[t] += red[t + s];
        __syncthreads();
    }
    float scale = rsqrtf(red[0] / (float)Dn + 1e-6f);
    float v0 = w[t] * a * scale;
    float v1 = w[t + 256] * b2 * scale;
    if (o) {
        o[(size_t)row * Dn + t]       = v0;
        o[(size_t)row * Dn + t + 256] = v1;
    }
    if (oh) {
        oh[(size_t)row * Dn + t]       = __float2half_rn(v0);
        oh[(size_t)row * Dn + t + 256] = __float2half_rn(v1);
    }
}

// ---------------- depthwise dilated conv -> fp16 -----------------------------
__global__ void dconv_k(const float* __restrict__ xn,
                        const float* __restrict__ dw,
                        const float* __restrict__ db,
                        __half* __restrict__ oh, int dil) {
    int idx = blockIdx.x * blockDim.x + threadIdx.x;
    if (idx >= BLD) return;
    int d  = idx & (Dn - 1);
    int bl = idx >> 9;
    int l  = bl & (Ln - 1);
    int b  = bl >> 11;
    float s = db[d];
#pragma unroll
    for (int k = 0; k < Kn; k++) {
        int t = l + (k - 2) * dil;
        if (t >= 0 && t < Ln)
            s += dw[d * Kn + k] * xn[(((size_t)(b * Ln + t)) << 9) + d];
    }
    oh[idx] = __float2half_rn(s);
}

// ---------------- recurrence: 3-phase chunked scan ---------------------------
__global__ void recur_part_k(const float* __restrict__ xn,
                             const float* __restrict__ alpha,
                             const float* __restrict__ beta,
                             float* __restrict__ pc) {
    int ch = blockIdx.x & (CHK - 1);
    int b  = blockIdx.x >> 7;
    int a  = threadIdx.x;
    float al = alpha[a], be = beta[a];
    const float* xp = xn + ((size_t)(b * Ln + ch * CLEN) << 9) + a;
    float h = 0.f;
#pragma unroll
    for (int i = 0; i < CLEN; i++) h = fmaf(al, h, be * xp[(size_t)i << 9]);
    pc[(b * CHK + ch) * An + a] = h;
}

__global__ void recur_scan_k(const float* __restrict__ pc,
                             const float* __restrict__ alpha,
                             float* __restrict__ pcx) {
    int t = threadIdx.x;
    int b = t >> 7;
    int a = t & 127;
    float al = alpha[a];
    float f = al;
#pragma unroll
    for (int q = 0; q < 4; q++) f *= f;
    float carry = 0.f;
    for (int ch = 0; ch < CHK; ch++) {
        int idx = (b * CHK + ch) * An + a;
        pcx[idx] = carry;
        carry = fmaf(f, carry, pc[idx]);
    }
}

__global__ void recur_apply_k(const float* __restrict__ xn,
                              const float* __restrict__ alpha,
                              const float* __restrict__ beta,
                              const float* __restrict__ pcx,
                              float* __restrict__ xs) {
    int ch = blockIdx.x & (CHK - 1);
    int b  = blockIdx.x >> 7;
    int a  = threadIdx.x;
    float al = alpha[a], be = beta[a];
    float h = pcx[(b * CHK + ch) * An + a];
    const float* xp = xn + ((size_t)(b * Ln + ch * CLEN) << 9) + a;
    float* op = xs + (size_t)(b * Ln + ch * CLEN) * An + a;
#pragma unroll
    for (int i = 0; i < CLEN; i++) {
        h = fmaf(al, h, be * xp[(size_t)i << 9]);
        op[i * An] = h;
    }
}

// ---------------- helpers ----------------------------------------------------
__device__ __forceinline__ void cp16(uint32_t dst, const void* src, bool pred) {
    asm volatile("cp.async.cg.shared.global [%0], [%1], 16, %2;\n"
                 :: "r"(dst), "l"(src), "r"(pred ? 16 : 0));
}
#define HMMA(acc, a, b)                                                        \
    asm volatile(                                                              \
        "mma.sync.aligned.m16n8k16.row.col.f32.f16.f16.f32 "                   \
        "{%0,%1,%2,%3}, {%4,%5,%6,%7}, {%8,%9}, {%0,%1,%2,%3};\n"              \
        : "+f"(acc[0]), "+f"(acc[1]), "+f"(acc[2]), "+f"(acc[3])               \
        : "r"(a[0]), "r"(a[1]), "r"(a[2]), "r"(a[3]), "r"(b[0]), "r"(b[1]))
#define LDSM4(r0, r1, r2, r3, addr)                                            \
    asm volatile("ldmatrix.sync.aligned.m8n8.x4.shared.b16 {%0,%1,%2,%3}, [%4];" \
                 : "=r"(r0), "=r"(r1), "=r"(r2), "=r"(r3) : "r"(addr))

// ---------------- fp16 GEMM, 128xBN tile, BK=64, 2-stage (R10-proven) --------
// EPI 0: C=v   EPI 1: gelu->Ch   EPI 2: C=C+add1+v
// EPI 3: C = v + (col<An ? add1[m*An+col] : aux[idx]);  Ch mirror
template <int EPI, int BN>
__global__ void __launch_bounds__(256)
gemm_h(const __half* __restrict__ A,
       const __half* __restrict__ Bw,
       const float* __restrict__ bias,
       const float* __restrict__ add1,
       const float* __restrict__ aux,
       float* __restrict__ C,
       __half* __restrict__ Ch,
       int M, int N, int K) {
    extern __shared__ uint32_t sm[];
    const uint32_t sbase = (uint32_t)__cvta_generic_to_shared(sm);
    const uint32_t bbase = sbase + 2 * 128 * SROW * 4;
    constexpr int NT = BN / 32;

    const int tid  = threadIdx.x;
    const int m0   = blockIdx.y * 128;
    const int n0   = blockIdx.x * BN;
    const int wid  = tid >> 5;
    const int lane = tid & 31;
    const int gid  = lane >> 2;
    const int tig  = lane & 3;
    const int mb   = (wid >> 2) * 64;
    const int nb   = (wid & 3) * (BN / 4);

    const uint32_t aoff = (((uint32_t)(lane & 15)) * SROW + ((lane >> 4) & 1) * 4) * 4;
    const uint32_t boff = (((uint32_t)((lane & 7) + ((lane >> 4) & 1) * 8)) * SROW
                           + ((lane >> 3) & 1) * 4) * 4;

    float acc[4][NT][4];
#pragma unroll
    for (int mt = 0; mt < 4; mt++)
#pragma unroll
        for (int nt = 0; nt < NT; nt++)
#pragma unroll
            for (int r = 0; r < 4; r++) acc[mt][nt][r] = 0.f;

    const int KT = K >> 6;

    auto issue = [&](int kt, int s) {
        int k0 = kt << 6;
#pragma unroll
        for (int j = 0; j < 4; j++) {
            int cid = tid + j * 256;
            int r   = cid >> 3;
            int col = cid & 7;
            cp16(sbase + ((s * 128 + r) * SROW + col * 4) * 4,
                 A + (size_t)(m0 + r) * K + k0 + col * 8, true);
        }
#pragma unroll
        for (int j = 0; j < BN / 32; j++) {
            int cid = tid + j * 256;
            int r   = cid >> 3;
            int col = cid & 7;
            int nr  = n0 + r;
            cp16(bbase + ((s * BN + r) * SROW + col * 4) * 4,
                 Bw + (size_t)(nr < N ? nr : 0) * K + k0 + col * 8, nr < N);
        }
    };

    issue(0, 0);
    asm volatile("cp.async.commit_group;\n");

    for (int kt = 0; kt < KT; kt++) {
        int s = kt & 1;
        if (kt + 1 < KT) {
            issue(kt + 1, s ^ 1);
            asm volatile("cp.async.commit_group;\n");
            asm volatile("cp.async.wait_group 1;\n");
        } else {
            asm volatile("cp.async.wait_group 0;\n");
        }
        __syncthreads();

        const uint32_t as0 = sbase + (uint32_t)(s * 128 * SROW * 4) + aoff;
        const uint32_t bs0 = bbase + (uint32_t)(s * BN * SROW * 4) + boff;
#pragma unroll
        for (int k8 = 0; k8 < 4; k8++) {
            const uint32_t ko4 = (uint32_t)(k8 * 8) * 4;
            uint32_t a[4][4], b[NT][2];
#pragma unroll
            for (int mt = 0; mt < 4; mt++)
                LDSM4(a[mt][0], a[mt][1], a[mt][2], a[mt][3],
                      as0 + (uint32_t)((mb + mt * 16) * SROW * 4) + ko4);
#pragma unroll
            for (int p = 0; p < NT / 2; p++)
                LDSM4(b[2*p][0], b[2*p][1], b[2*p+1][0], b[2*p+1][1],
                      bs0 + (uint32_t)((nb + p * 16) * SROW * 4) + ko4);
#pragma unroll
            for (int mt = 0; mt < 4; mt++)
#pragma unroll
                for (int nt = 0; nt < NT; nt++)
                    HMMA(acc[mt][nt], a[mt], b[nt]);
        }
        __syncthreads();
    }

#pragma unroll
    for (int mt = 0; mt < 4; mt++) {
        int row0 = m0 + mb + mt * 16 + gid;
#pragma unroll
        for (int nt = 0; nt < NT; nt++) {
            int col0 = n0 + nb + nt * 8 + tig * 2;
#pragma unroll
            for (int hf = 0; hf < 2; hf++) {
                int rr = row0 + hf * 8;
#pragma unroll
                for (int cc = 0; cc < 2; cc++) {
                    int col = col0 + cc;
                    if (col < N) {
                        float v = acc[mt][nt][hf * 2 + cc] + (bias ? bias[col] : 0.f);
                        size_t idx = (size_t)rr * N + col;
                        if (EPI == 0) {
                            C[idx] = v;
                        } else if (EPI == 1) {
                            float g = 0.5f * v * (1.f + erff(v * 0.70710678118654752f));
                            Ch[idx] = __float2half_rn(g);
                        } else if (EPI == 2) {
                            C[idx] = C[idx] + add1[idx] + v;
                        } else {
                            float r = (col < An) ? add1[(size_t)rr * An + col]
                                                 : aux[idx];
                            float o = v + r;
                            C[idx]  = o;
                            Ch[idx] = __float2half_rn(o);
                        }
                    }
                }
            }
        }
    }
}

// ---------------- fused w1|w2 GEMM + GLU (2-stage, proven) -------------------
__global__ void __launch_bounds__(256)
w1w2glu_k(const __half* __restrict__ Ah,
          const __half* __restrict__ W1,
          const __half* __restrict__ W2,
          const float* __restrict__ b1,
          const float* __restrict__ b2,
          float* __restrict__ y,
          __half* __restrict__ yh) {
    extern __shared__ uint32_t sm[];
    const uint32_t sbase  = (uint32_t)__cvta_generic_to_shared(sm);
    const uint32_t b1base = sbase + 2 * 128 * SROW * 4;
    const uint32_t b2base = sbase + 4 * 128 * SROW * 4;

    const int tid  = threadIdx.x;
    const int m0   = blockIdx.y * 128;
    const int n0   = blockIdx.x * 128;
    const int wid  = tid >> 5;
    const int lane = tid & 31;
    const int gid  = lane >> 2;
    const int tig  = lane & 3;
    const int mb   = (wid >> 2) * 64;
    const int nb   = (wid & 3) * 32;
    const int K    = Dn;

    const uint32_t aoff = (((uint32_t)(lane & 15)) * SROW + ((lane >> 4) & 1) * 4) * 4;
    const uint32_t boff = (((uint32_t)((lane & 7) + ((lane >> 4) & 1) * 8)) * SROW
                           + ((lane >> 3) & 1) * 4) * 4;

    float acc1[4][4][4], acc2[4][4][4];
#pragma unroll
    for (int mt = 0; mt < 4; mt++)
#pragma unroll
        for (int nt = 0; nt < 4; nt++)
#pragma unroll
            for (int r = 0; r < 4; r++) { acc1[mt][nt][r] = 0.f; acc2[mt][nt][r] = 0.f; }

    const int KT = K >> 6;

    auto issue = [&](int kt, int s) {
        int k0 = kt << 6;
#pragma unroll
        for (int j = 0; j < 4; j++) {
            int cid = tid + j * 256;
            int r   = cid >> 3;
            int col = cid & 7;
            uint32_t so = ((s * 128 + r) * SROW + col * 4) * 4;
            cp16(sbase  + so, Ah + (size_t)(m0 + r) * K + k0 + col * 8, true);
            cp16(b1base + so, W1 + (size_t)(n0 + r) * K + k0 + col * 8, true);
            cp16(b2base + so, W2 + (size_t)(n0 + r) * K + k0 + col * 8, true);
        }
    };

    issue(0, 0);
    asm volatile("cp.async.commit_group;\n");

    for (int kt = 0; kt < KT; kt++) {
        int s = kt & 1;
        if (kt + 1 < KT) {
            issue(kt + 1, s ^ 1);
            asm volatile("cp.async.commit_group;\n");
            asm volatile("cp.async.wait_group 1;\n");
        } else {
            asm volatile("cp.async.wait_group 0;\n");
        }
        __syncthreads();

        const uint32_t as0  = sbase  + (uint32_t)(s * 128 * SROW * 4) + aoff;
        const uint32_t b1s0 = b1base + (uint32_t)(s * 128 * SROW * 4) + boff;
        const uint32_t b2s0 = b2base + (uint32_t)(s * 128 * SROW * 4) + boff;
#pragma unroll
        for (int k8 = 0; k8 < 4; k8++) {
            const uint32_t ko4 = (uint32_t)(k8 * 8) * 4;
            uint32_t a[4][4], br1[4][2], br2[4][2];
#pragma unroll
            for (int mt = 0; mt < 4; mt++)
                LDSM4(a[mt][0], a[mt][1], a[mt][2], a[mt][3],
                      as0 + (uint32_t)((mb + mt * 16) * SROW * 4) + ko4);
#pragma unroll
            for (int p = 0; p < 2; p++) {
                LDSM4(br1[2*p][0], br1[2*p][1], br1[2*p+1][0], br1[2*p+1][1],
                      b1s0 + (uint32_t)((nb + p * 16) * SROW * 4) + ko4);
                LDSM4(br2[2*p][0], br2[2*p][1], br2[2*p+1][0], br2[2*p+1][1],
                      b2s0 + (uint32_t)((nb + p * 16) * SROW * 4) + ko4);
            }
#pragma unroll
            for (int mt = 0; mt < 4; mt++)
#pragma unroll
                for (int nt = 0; nt < 4; nt++) {
                    HMMA(acc1[mt][nt], a[mt], br1[nt]);
                    HMMA(acc2[mt][nt], a[mt], br2[nt]);
                }
        }
        __syncthreads();
    }

#pragma unroll
    for (int mt = 0; mt < 4; mt++) {
        int row0 = m0 + mb + mt * 16 + gid;
#pragma unroll
        for (int nt = 0; nt < 4; nt++) {
            int col0 = n0 + nb + nt * 8 + tig * 2;
#pragma unroll
            for (int hf = 0; hf < 2; hf++) {
                int rr = row0 + hf * 8;
#pragma unroll
                for (int cc = 0; cc < 2; cc++) {
                    int col = col0 + cc;
                    float v1 = acc1[mt][nt][hf * 2 + cc] + b1[col];
                    float v2 = acc2[mt][nt][hf * 2 + cc] + b2[col];
                    size_t idx = (size_t)rr * Dn + col;
                    float o = y[idx] + (1.f / (1.f + expf(-v1))) * tanhf(v2);
                    y[idx]  = o;
                    yh[idx] = __float2half_rn(o);
                }
            }
        }
    }
}

// ---------------- host ------------------------------------------------------
extern "C" void kernel_launch(void* const* d_in, const int* in_sizes, int n_in,
                              void* d_out, int out_size) {
    const int*   tokens  = (const int*)  d_in[0];
    const float* emb     = (const float*)d_in[1];
    const float* norm_w  = (const float*)d_in[2];
    const float* dconv_w = (const float*)d_in[3];
    const float* dconv_b = (const float*)d_in[4];
    const float* pconv_w = (const float*)d_in[5];
    const float* pconv_b = (const float*)d_in[6];
    const float* alpha   = (const float*)d_in[7];
    const float* beta    = (const float*)d_in[8];
    const float* w1      = (const float*)d_in[9];
    const float* b1      = (const float*)d_in[10];
    const float* w2      = (const float*)d_in[11];
    const float* b2      = (const float*)d_in[12];
    const float* down_w  = (const float*)d_in[13];
    const float* down_b  = (const float*)d_in[14];
    const float* up_w    = (const float*)d_in[15];
    const float* up_b    = (const float*)d_in[16];
    const float* fnw     = (const float*)d_in[17];
    float* out = (float*)d_out;

    float *x, *xn, *y, *xs, *pc, *pcx;
    __half *t1h, *yh, *hdnh, *xnh, *embh, *pwh, *w1h, *w2h, *dnh, *uph;
    cudaGetSymbolAddress((void**)&x,    g_x);
    cudaGetSymbolAddress((void**)&xn,   g_xn);
    cudaGetSymbolAddress((void**)&y,    g_y);
    cudaGetSymbolAddress((void**)&xs,   g_xs);
    cudaGetSymbolAddress((void**)&pc,   g_pc);
    cudaGetSymbolAddress((void**)&pcx,  g_pcx);
    cudaGetSymbolAddress((void**)&t1h,  g_t1h);
    cudaGetSymbolAddress((void**)&yh,   g_yh);
    cudaGetSymbolAddress((void**)&hdnh, g_hdnh);
    cudaGetSymbolAddress((void**)&xnh,  g_xnh);
    cudaGetSymbolAddress((void**)&embh, g_embh);
    cudaGetSymbolAddress((void**)&pwh,  g_pwh);
    cudaGetSymbolAddress((void**)&w1h,  g_w1h);
    cudaGetSymbolAddress((void**)&w2h,  g_w2h);
    cudaGetSymbolAddress((void**)&dnh,  g_dnh);
    cudaGetSymbolAddress((void**)&uph,  g_uph);

    cudaFuncSetAttribute(gemm_h<1,128>, cudaFuncAttributeMaxDynamicSharedMemorySize, GEMM_SMEM);
    cudaFuncSetAttribute(gemm_h<2,128>, cudaFuncAttributeMaxDynamicSharedMemorySize, GEMM_SMEM);
    cudaFuncSetAttribute(gemm_h<3,128>, cudaFuncAttributeMaxDynamicSharedMemorySize, GEMM_SMEM);
    cudaFuncSetAttribute(gemm_h<0,256>, cudaFuncAttributeMaxDynamicSharedMemorySize, LOGIT_SMEM);
    cudaFuncSetAttribute(w1w2glu_k,     cudaFuncAttributeMaxDynamicSharedMemorySize, DUAL_SMEM);

    const int egrid = (BLD + 255) / 256;

    {
        int n;
        n = Vn * Dn / 4;        f2h_k<<<(n + 255) / 256, 256>>>(emb,     embh, n);
        n = NLn * Dn * Dn / 4;  f2h_k<<<(n + 255) / 256, 256>>>(pconv_w, pwh,  n);
        n = NLn * Dn * Dn / 4;  f2h_k<<<(n + 255) / 256, 256>>>(w1,      w1h,  n);
        n = NLn * Dn * Dn / 4;  f2h_k<<<(n + 255) / 256, 256>>>(w2,      w2h,  n);
        n = NLn * Hn * Dn / 4;  f2h_k<<<(n + 255) / 256, 256>>>(down_w,  dnh,  n);
        n = NLn * Dn * Hn / 4;  f2h_k<<<(n + 255) / 256, 256>>>(up_w,    uph,  n);
    }

    embed_rope_k<<<egrid, 256>>>(tokens, emb, x);

    for (int i = 0; i < NLn; i++) {
        int dil = 1 << (i % 3);
        rmsnorm_k<<<BLn, 256>>>(x, norm_w + i * Dn, xn, nullptr);
        dconv_k<<<egrid, 256>>>(xn, dconv_w + (size_t)i * Dn * Kn,
                                dconv_b + i * Dn, t1h, dil);
        recur_part_k<<<Bn * CHK, An>>>(xn, alpha + i * An, beta + i * An, pc);
        recur_scan_k<<<1, 256>>>(pc, alpha + i * An, pcx);
        recur_apply_k<<<Bn * CHK, An>>>(xn, alpha + i * An, beta + i * An, pcx, xs);

        dim3 gpw(Dn / 128, BLn / 128);  // (4, 32)
        gemm_h<3,128><<<gpw, 256, GEMM_SMEM>>>(
            t1h, pwh + (size_t)i * Dn * Dn, pconv_b + i * Dn,
            xs, xn, y, yh, BLn, Dn, Dn);

        w1w2glu_k<<<gpw, 256, DUAL_SMEM>>>(
            yh, w1h + (size_t)i * Dn * Dn, w2h + (size_t)i * Dn * Dn,
            b1 + i * Dn, b2 + i * Dn, y, yh);

        dim3 gdn(Hn / 128, BLn / 128);  // (1, 32)
        gemm_h<1,128><<<gdn, 256, GEMM_SMEM>>>(
            yh, dnh + (size_t)i * Hn * Dn, down_b + i * Hn,
            nullptr, nullptr, nullptr, hdnh, BLn, Hn, Dn);

        gemm_h<2,128><<<gpw, 256, GEMM_SMEM>>>(
            hdnh, uph + (size_t)i * Dn * Hn, up_b + i * Dn,
            y, nullptr, x, nullptr, BLn, Dn, Hn);
    }

    rmsnorm_k<<<BLn, 256>>>(x, fnw, nullptr, xnh);
    dim3 gl((Vn + 255) / 256, BLn / 128);  // (197, 32)
    gemm_h<0,256><<<gl, 256, LOGIT_SMEM>>>(
        xnh, embh, nullptr, nullptr, nullptr, out, nullptr, BLn, Vn, Dn);
}

// round 13
// speedup vs baseline: 1.3679x; 1.0618x over previous
#include <cuda_runtime.h>
#include <cuda_fp16.h>
#include <cstdint>
#include <math.h>

#define Bn 2
#define Ln 2048
#define Dn 512
#define Vn 50257
#define NLn 12
#define Kn 5
#define An 128
#define Hn 128
#define BLn (Bn*Ln)
#define BLD (Bn*Ln*Dn)
#define CHK 128
#define CLEN 16
#define EGRIDC (BLD / 256)                        /* 8192 dconv blocks */

#define SROW 36                                   /* u32 per smem row */
#define GEMM_SMEM  (2 * 2 * 128 * SROW * 4)       /* 73,728 B  */
#define DUAL_SMEM  (2 * 3 * 128 * SROW * 4)       /* 110,592 B */

// ---------------- scratch (device globals) -----------------------------------
__device__ __align__(16) float  g_x[BLD];
__device__ __align__(16) float  g_xn[BLD];
__device__ __align__(16) float  g_y[BLD];
__device__ __align__(16) float  g_xs[Bn*Ln*An];
__device__ __align__(16) float  g_pc [Bn*CHK*An];
__device__ __align__(16) __half g_t1h[BLD];
__device__ __align__(16) __half g_yh[BLD];
__device__ __align__(16) __half g_hdnh[Bn*Ln*Hn];
__device__ __align__(16) __half g_xnh[BLD];
__device__ __align__(16) __half g_embh[Vn*Dn];
__device__ __align__(16) __half g_pwh [NLn*Dn*Dn];
__device__ __align__(16) __half g_w1h [NLn*Dn*Dn];
__device__ __align__(16) __half g_w2h [NLn*Dn*Dn];
__device__ __align__(16) __half g_dnh [NLn*Hn*Dn];
__device__ __align__(16) __half g_uph [NLn*Dn*Hn];

// ---------------- fp32 -> fp16 -----------------------------------------------
__global__ void f2h_k(const float* __restrict__ src, __half* __restrict__ dst,
                      int n4) {
    int i = blockIdx.x * blockDim.x + threadIdx.x;
    if (i >= n4) return;
    float4 v = ((const float4*)src)[i];
    ((__half2*)dst)[i * 2]     = __floats2half2_rn(v.x, v.y);
    ((__half2*)dst)[i * 2 + 1] = __floats2half2_rn(v.z, v.w);
}

// ---------------- embedding + rope ------------------------------------------
__global__ void embed_rope_k(const int* __restrict__ tok,
                             const float* __restrict__ emb,
                             float* __restrict__ x) {
    int idx = blockIdx.x * blockDim.x + threadIdx.x;
    if (idx >= BLD) return;
    int d  = idx & (Dn - 1);
    int bl = idx >> 9;
    int l  = bl & (Ln - 1);
    int t  = tok[bl];
    const float* e = emb + (size_t)t * Dn;
    const int half = Dn / 2;
    int fi = (d < half) ? d : d - half;
    float invf = powf(10000.f, -(float)fi / (float)half);
    float ang  = (float)l * invf;
    float s, c;
    sincosf(ang, &s, &c);
    float v = e[d];
    float partner = (d < half) ? -e[d + half] : e[d - half];
    x[idx] = v * c + partner * s;
}

// ---------------- rmsnorm ----------------------------------------------------
__global__ void rmsnorm_k(const float* __restrict__ x,
                          const float* __restrict__ w,
                          float* __restrict__ o,
                          __half* __restrict__ oh) {
    int row = blockIdx.x;
    int t = threadIdx.x;
    const float* xr = x + (size_t)row * Dn;
    float a  = xr[t];
    float b2 = xr[t + 256];
    __shared__ float red[256];
    red[t] = a * a + b2 * b2;
    __syncthreads();
    for (int s = 128; s > 0; s >>= 1) {
        if (t < s) red[t] += red[t + s];
        __syncthreads();
    }
    float scale = rsqrtf(red[0] / (float)Dn + 1e-6f);
    float v0 = w[t] * a * scale;
    float v1 = w[t + 256] * b2 * scale;
    if (o) {
        o[(size_t)row * Dn + t]       = v0;
        o[(size_t)row * Dn + t + 256] = v1;
    }
    if (oh) {
        oh[(size_t)row * Dn + t]       = __float2half_rn(v0);
        oh[(size_t)row * Dn + t + 256] = __float2half_rn(v1);
    }
}

// ---------------- fused dconv + recurrence chunk-sums ------------------------
// blocks [0, EGRIDC): depthwise dilated conv -> t1h
// blocks [EGRIDC, EGRIDC+Bn*CHK): chunk partial sums -> pc (threads < An)
__global__ void dconv_part_k(const float* __restrict__ xn,
                             const float* __restrict__ dw,
                             const float* __restrict__ db,
                             const float* __restrict__ alpha,
                             const float* __restrict__ beta,
                             __half* __restrict__ t1h,
                             float* __restrict__ pc,
                             int dil) {
    int bid = blockIdx.x;
    if (bid < EGRIDC) {
        int idx = bid * 256 + threadIdx.x;
        int d  = idx & (Dn - 1);
        int bl = idx >> 9;
        int l  = bl & (Ln - 1);
        int b  = bl >> 11;
        float s = db[d];
#pragma unroll
        for (int k = 0; k < Kn; k++) {
            int t = l + (k - 2) * dil;
            if (t >= 0 && t < Ln)
                s += dw[d * Kn + k] * xn[(((size_t)(b * Ln + t)) << 9) + d];
        }
        t1h[idx] = __float2half_rn(s);
    } else if (threadIdx.x < An) {
        int r  = bid - EGRIDC;              // 0..Bn*CHK-1
        int ch = r & (CHK - 1);
        int b  = r >> 7;
        int a  = threadIdx.x;
        float al = alpha[a], be = beta[a];
        const float* xp = xn + ((size_t)(b * Ln + ch * CLEN) << 9) + a;
        float h = 0.f;
#pragma unroll
        for (int i = 0; i < CLEN; i++) h = fmaf(al, h, be * xp[(size_t)i << 9]);
        pc[(b * CHK + ch) * An + a] = h;
    }
}

// ---------------- fused carry-recompute + apply ------------------------------
// block (b,ch): fold pc[0..ch) for the carry (same fma order as the old
// serial scan -> bit-identical), then apply CLEN steps.
__global__ void scan_apply_k(const float* __restrict__ xn,
                             const float* __restrict__ alpha,
                             const float* __restrict__ beta,
                             const float* __restrict__ pc,
                             float* __restrict__ xs) {
    int ch = blockIdx.x & (CHK - 1);
    int b  = blockIdx.x >> 7;
    int a  = threadIdx.x;                   // 128
    float al = alpha[a], be = beta[a];
    float f = al;
#pragma unroll
    for (int q = 0; q < 4; q++) f *= f;     // al^16
    float h = 0.f;
    const float* pp = pc + (size_t)b * CHK * An + a;
    for (int c = 0; c < ch; c++)
        h = fmaf(f, h, pp[(size_t)c * An]);
    const float* xp = xn + ((size_t)(b * Ln + ch * CLEN) << 9) + a;
    float* op = xs + (size_t)(b * Ln + ch * CLEN) * An + a;
#pragma unroll
    for (int i = 0; i < CLEN; i++) {
        h = fmaf(al, h, be * xp[(size_t)i << 9]);
        op[i * An] = h;
    }
}

// ---------------- helpers ----------------------------------------------------
__device__ __forceinline__ void cp16(uint32_t dst, const void* src, bool pred) {
    asm volatile("cp.async.cg.shared.global [%0], [%1], 16, %2;\n"
                 :: "r"(dst), "l"(src), "r"(pred ? 16 : 0));
}
#define HMMA(acc, a, b)                                                        \
    asm volatile(                                                              \
        "mma.sync.aligned.m16n8k16.row.col.f32.f16.f16.f32 "                   \
        "{%0,%1,%2,%3}, {%4,%5,%6,%7}, {%8,%9}, {%0,%1,%2,%3};\n"              \
        : "+f"(acc[0]), "+f"(acc[1]), "+f"(acc[2]), "+f"(acc[3])               \
        : "r"(a[0]), "r"(a[1]), "r"(a[2]), "r"(a[3]), "r"(b[0]), "r"(b[1]))
#define LDSM4(r0, r1, r2, r3, addr)                                            \
    asm volatile("ldmatrix.sync.aligned.m8n8.x4.shared.b16 {%0,%1,%2,%3}, [%4];" \
                 : "=r"(r0), "=r"(r1), "=r"(r2), "=r"(r3) : "r"(addr))

// ---------------- fp16 GEMM, 128x128 tile, BK=64, 2-stage (R10-proven) -------
// EPI 0: C=v   EPI 1: gelu->Ch   EPI 2: C=C+add1+v
// EPI 3: C = v + (col<An ? add1[m*An+col] : aux[idx]);  Ch mirror
template <int EPI>
__global__ void __launch_bounds__(256)
gemm_h(const __half* __restrict__ A,
       const __half* __restrict__ Bw,
       const float* __restrict__ bias,
       const float* __restrict__ add1,
       const float* __restrict__ aux,
       float* __restrict__ C,
       __half* __restrict__ Ch,
       int M, int N, int K) {
    extern __shared__ uint32_t sm[];
    const uint32_t sbase = (uint32_t)__cvta_generic_to_shared(sm);
    const uint32_t bbase = sbase + 2 * 128 * SROW * 4;

    const int tid  = threadIdx.x;
    const int m0   = blockIdx.y * 128;
    const int n0   = blockIdx.x * 128;
    const int wid  = tid >> 5;
    const int lane = tid & 31;
    const int gid  = lane >> 2;
    const int tig  = lane & 3;
    const int mb   = (wid >> 2) * 64;
    const int nb   = (wid & 3) * 32;

    const uint32_t aoff = (((uint32_t)(lane & 15)) * SROW + ((lane >> 4) & 1) * 4) * 4;
    const uint32_t boff = (((uint32_t)((lane & 7) + ((lane >> 4) & 1) * 8)) * SROW
                           + ((lane >> 3) & 1) * 4) * 4;

    float acc[4][4][4];
#pragma unroll
    for (int mt = 0; mt < 4; mt++)
#pragma unroll
        for (int nt = 0; nt < 4; nt++)
#pragma unroll
            for (int r = 0; r < 4; r++) acc[mt][nt][r] = 0.f;

    const int KT = K >> 6;

    auto issue = [&](int kt, int s) {
        int k0 = kt << 6;
#pragma unroll
        for (int j = 0; j < 4; j++) {
            int cid = tid + j * 256;
            int r   = cid >> 3;
            int col = cid & 7;
            cp16(sbase + ((s * 128 + r) * SROW + col * 4) * 4,
                 A + (size_t)(m0 + r) * K + k0 + col * 8, true);
            int nr = n0 + r;
            cp16(bbase + ((s * 128 + r) * SROW + col * 4) * 4,
                 Bw + (size_t)(nr < N ? nr : 0) * K + k0 + col * 8, nr < N);
        }
    };

    issue(0, 0);
    asm volatile("cp.async.commit_group;\n");

    for (int kt = 0; kt < KT; kt++) {
        int s = kt & 1;
        if (kt + 1 < KT) {
            issue(kt + 1, s ^ 1);
            asm volatile("cp.async.commit_group;\n");
            asm volatile("cp.async.wait_group 1;\n");
        } else {
            asm volatile("cp.async.wait_group 0;\n");
        }
        __syncthreads();

        const uint32_t as0 = sbase + (uint32_t)(s * 128 * SROW * 4) + aoff;
        const uint32_t bs0 = bbase + (uint32_t)(s * 128 * SROW * 4) + boff;
#pragma unroll
        for (int k8 = 0; k8 < 4; k8++) {
            const uint32_t ko4 = (uint32_t)(k8 * 8) * 4;
            uint32_t a[4][4], b[4][2];
#pragma unroll
            for (int mt = 0; mt < 4; mt++)
                LDSM4(a[mt][0], a[mt][1], a[mt][2], a[mt][3],
                      as0 + (uint32_t)((mb + mt * 16) * SROW * 4) + ko4);
#pragma unroll
            for (int p = 0; p < 2; p++)
                LDSM4(b[2*p][0], b[2*p][1], b[2*p+1][0], b[2*p+1][1],
                      bs0 + (uint32_t)((nb + p * 16) * SROW * 4) + ko4);
#pragma unroll
            for (int mt = 0; mt < 4; mt++)
#pragma unroll
                for (int nt = 0; nt < 4; nt++)
                    HMMA(acc[mt][nt], a[mt], b[nt]);
        }
        __syncthreads();
    }

#pragma unroll
    for (int mt = 0; mt < 4; mt++) {
        int row0 = m0 + mb + mt * 16 + gid;
#pragma unroll
        for (int nt = 0; nt < 4; nt++) {
            int col0 = n0 + nb + nt * 8 + tig * 2;
#pragma unroll
            for (int hf = 0; hf < 2; hf++) {
                int rr = row0 + hf * 8;
#pragma unroll
                for (int cc = 0; cc < 2; cc++) {
                    int col = col0 + cc;
                    if (col < N) {
                        float v = acc[mt][nt][hf * 2 + cc] + (bias ? bias[col] : 0.f);
                        size_t idx = (size_t)rr * N + col;
                        if (EPI == 0) {
                            C[idx] = v;
                        } else if (EPI == 1) {
                            float g = 0.5f * v * (1.f + erff(v * 0.70710678118654752f));
                            Ch[idx] = __float2half_rn(g);
                        } else if (EPI == 2) {
                            C[idx] = C[idx] + add1[idx] + v;
                        } else {
                            float r = (col < An) ? add1[(size_t)rr * An + col]
                                                 : aux[idx];
                            float o = v + r;
                            C[idx]  = o;
                            Ch[idx] = __float2half_rn(o);
                        }
                    }
                }
            }
        }
    }
}

// ---------------- fused w1|w2 GEMM + GLU (2-stage, proven) -------------------
__global__ void __launch_bounds__(256)
w1w2glu_k(const __half* __restrict__ Ah,
          const __half* __restrict__ W1,
          const __half* __restrict__ W2,
          const float* __restrict__ b1,
          const float* __restrict__ b2,
          float* __restrict__ y,
          __half* __restrict__ yh) {
    extern __shared__ uint32_t sm[];
    const uint32_t sbase  = (uint32_t)__cvta_generic_to_shared(sm);
    const uint32_t b1base = sbase + 2 * 128 * SROW * 4;
    const uint32_t b2base = sbase + 4 * 128 * SROW * 4;

    const int tid  = threadIdx.x;
    const int m0   = blockIdx.y * 128;
    const int n0   = blockIdx.x * 128;
    const int wid  = tid >> 5;
    const int lane = tid & 31;
    const int gid  = lane >> 2;
    const int tig  = lane & 3;
    const int mb   = (wid >> 2) * 64;
    const int nb   = (wid & 3) * 32;
    const int K    = Dn;

    const uint32_t aoff = (((uint32_t)(lane & 15)) * SROW + ((lane >> 4) & 1) * 4) * 4;
    const uint32_t boff = (((uint32_t)((lane & 7) + ((lane >> 4) & 1) * 8)) * SROW
                           + ((lane >> 3) & 1) * 4) * 4;

    float acc1[4][4][4], acc2[4][4][4];
#pragma unroll
    for (int mt = 0; mt < 4; mt++)
#pragma unroll
        for (int nt = 0; nt < 4; nt++)
#pragma unroll
            for (int r = 0; r < 4; r++) { acc1[mt][nt][r] = 0.f; acc2[mt][nt][r] = 0.f; }

    const int KT = K >> 6;

    auto issue = [&](int kt, int s) {
        int k0 = kt << 6;
#pragma unroll
        for (int j = 0; j < 4; j++) {
            int cid = tid + j * 256;
            int r   = cid >> 3;
            int col = cid & 7;
            uint32_t so = ((s * 128 + r) * SROW + col * 4) * 4;
            cp16(sbase  + so, Ah + (size_t)(m0 + r) * K + k0 + col * 8, true);
            cp16(b1base + so, W1 + (size_t)(n0 + r) * K + k0 + col * 8, true);
            cp16(b2base + so, W2 + (size_t)(n0 + r) * K + k0 + col * 8, true);
        }
    };

    issue(0, 0);
    asm volatile("cp.async.commit_group;\n");

    for (int kt = 0; kt < KT; kt++) {
        int s = kt & 1;
        if (kt + 1 < KT) {
            issue(kt + 1, s ^ 1);
            asm volatile("cp.async.commit_group;\n");
            asm volatile("cp.async.wait_group 1;\n");
        } else {
            asm volatile("cp.async.wait_group 0;\n");
        }
        __syncthreads();

        const uint32_t as0  = sbase  + (uint32_t)(s * 128 * SROW * 4) + aoff;
        const uint32_t b1s0 = b1base + (uint32_t)(s * 128 * SROW * 4) + boff;
        const uint32_t b2s0 = b2base + (uint32_t)(s * 128 * SROW * 4) + boff;
#pragma unroll
        for (int k8 = 0; k8 < 4; k8++) {
            const uint32_t ko4 = (uint32_t)(k8 * 8) * 4;
            uint32_t a[4][4], br1[4][2], br2[4][2];
#pragma unroll
            for (int mt = 0; mt < 4; mt++)
                LDSM4(a[mt][0], a[mt][1], a[mt][2], a[mt][3],
                      as0 + (uint32_t)((mb + mt * 16) * SROW * 4) + ko4);
#pragma unroll
            for (int p = 0; p < 2; p++) {
                LDSM4(br1[2*p][0], br1[2*p][1], br1[2*p+1][0], br1[2*p+1][1],
                      b1s0 + (uint32_t)((nb + p * 16) * SROW * 4) + ko4);
                LDSM4(br2[2*p][0], br2[2*p][1], br2[2*p+1][0], br2[2*p+1][1],
                      b2s0 + (uint32_t)((nb + p * 16) * SROW * 4) + ko4);
            }
#pragma unroll
            for (int mt = 0; mt < 4; mt++)
#pragma unroll
                for (int nt = 0; nt < 4; nt++) {
                    HMMA(acc1[mt][nt], a[mt], br1[nt]);
                    HMMA(acc2[mt][nt], a[mt], br2[nt]);
                }
        }
        __syncthreads();
    }

#pragma unroll
    for (int mt = 0; mt < 4; mt++) {
        int row0 = m0 + mb + mt * 16 + gid;
#pragma unroll
        for (int nt = 0; nt < 4; nt++) {
            int col0 = n0 + nb + nt * 8 + tig * 2;
#pragma unroll
            for (int hf = 0; hf < 2; hf++) {
                int rr = row0 + hf * 8;
#pragma unroll
                for (int cc = 0; cc < 2; cc++) {
                    int col = col0 + cc;
                    float v1 = acc1[mt][nt][hf * 2 + cc] + b1[col];
                    float v2 = acc2[mt][nt][hf * 2 + cc] + b2[col];
                    size_t idx = (size_t)rr * Dn + col;
                    float o = y[idx] + (1.f / (1.f + expf(-v1))) * tanhf(v2);
                    y[idx]  = o;
                    yh[idx] = __float2half_rn(o);
                }
            }
        }
    }
}

// ---------------- host ------------------------------------------------------
extern "C" void kernel_launch(void* const* d_in, const int* in_sizes, int n_in,
                              void* d_out, int out_size) {
    const int*   tokens  = (const int*)  d_in[0];
    const float* emb     = (const float*)d_in[1];
    const float* norm_w  = (const float*)d_in[2];
    const float* dconv_w = (const float*)d_in[3];
    const float* dconv_b = (const float*)d_in[4];
    const float* pconv_w = (const float*)d_in[5];
    const float* pconv_b = (const float*)d_in[6];
    const float* alpha   = (const float*)d_in[7];
    const float* beta    = (const float*)d_in[8];
    const float* w1      = (const float*)d_in[9];
    const float* b1      = (const float*)d_in[10];
    const float* w2      = (const float*)d_in[11];
    const float* b2      = (const float*)d_in[12];
    const float* down_w  = (const float*)d_in[13];
    const float* down_b  = (const float*)d_in[14];
    const float* up_w    = (const float*)d_in[15];
    const float* up_b    = (const float*)d_in[16];
    const float* fnw     = (const float*)d_in[17];
    float* out = (float*)d_out;

    float *x, *xn, *y, *xs, *pc;
    __half *t1h, *yh, *hdnh, *xnh, *embh, *pwh, *w1h, *w2h, *dnh, *uph;
    cudaGetSymbolAddress((void**)&x,    g_x);
    cudaGetSymbolAddress((void**)&xn,   g_xn);
    cudaGetSymbolAddress((void**)&y,    g_y);
    cudaGetSymbolAddress((void**)&xs,   g_xs);
    cudaGetSymbolAddress((void**)&pc,   g_pc);
    cudaGetSymbolAddress((void**)&t1h,  g_t1h);
    cudaGetSymbolAddress((void**)&yh,   g_yh);
    cudaGetSymbolAddress((void**)&hdnh, g_hdnh);
    cudaGetSymbolAddress((void**)&xnh,  g_xnh);
    cudaGetSymbolAddress((void**)&embh, g_embh);
    cudaGetSymbolAddress((void**)&pwh,  g_pwh);
    cudaGetSymbolAddress((void**)&w1h,  g_w1h);
    cudaGetSymbolAddress((void**)&w2h,  g_w2h);
    cudaGetSymbolAddress((void**)&dnh,  g_dnh);
    cudaGetSymbolAddress((void**)&uph,  g_uph);

    cudaFuncSetAttribute(gemm_h<0>, cudaFuncAttributeMaxDynamicSharedMemorySize, GEMM_SMEM);
    cudaFuncSetAttribute(gemm_h<1>, cudaFuncAttributeMaxDynamicSharedMemorySize, GEMM_SMEM);
    cudaFuncSetAttribute(gemm_h<2>, cudaFuncAttributeMaxDynamicSharedMemorySize, GEMM_SMEM);
    cudaFuncSetAttribute(gemm_h<3>, cudaFuncAttributeMaxDynamicSharedMemorySize, GEMM_SMEM);
    cudaFuncSetAttribute(w1w2glu_k, cudaFuncAttributeMaxDynamicSharedMemorySize, DUAL_SMEM);

    {
        int n;
        n = Vn * Dn / 4;        f2h_k<<<(n + 255) / 256, 256>>>(emb,     embh, n);
        n = NLn * Dn * Dn / 4;  f2h_k<<<(n + 255) / 256, 256>>>(pconv_w, pwh,  n);
        n = NLn * Dn * Dn / 4;  f2h_k<<<(n + 255) / 256, 256>>>(w1,      w1h,  n);
        n = NLn * Dn * Dn / 4;  f2h_k<<<(n + 255) / 256, 256>>>(w2,      w2h,  n);
        n = NLn * Hn * Dn / 4;  f2h_k<<<(n + 255) / 256, 256>>>(down_w,  dnh,  n);
        n = NLn * Dn * Hn / 4;  f2h_k<<<(n + 255) / 256, 256>>>(up_w,    uph,  n);
    }

    embed_rope_k<<<EGRIDC, 256>>>(tokens, emb, x);

    for (int i = 0; i < NLn; i++) {
        int dil = 1 << (i % 3);
        rmsnorm_k<<<BLn, 256>>>(x, norm_w + i * Dn, xn, nullptr);
        dconv_part_k<<<EGRIDC + Bn * CHK, 256>>>(
            xn, dconv_w + (size_t)i * Dn * Kn, dconv_b + i * Dn,
            alpha + i * An, beta + i * An, t1h, pc, dil);
        scan_apply_k<<<Bn * CHK, An>>>(xn, alpha + i * An, beta + i * An,
                                       pc, xs);

        dim3 gpw(Dn / 128, BLn / 128);  // (4, 32)
        gemm_h<3><<<gpw, 256, GEMM_SMEM>>>(
            t1h, pwh + (size_t)i * Dn * Dn, pconv_b + i * Dn,
            xs, xn, y, yh, BLn, Dn, Dn);

        w1w2glu_k<<<gpw, 256, DUAL_SMEM>>>(
            yh, w1h + (size_t)i * Dn * Dn, w2h + (size_t)i * Dn * Dn,
            b1 + i * Dn, b2 + i * Dn, y, yh);

        dim3 gdn(Hn / 128, BLn / 128);  // (1, 32)
        gemm_h<1><<<gdn, 256, GEMM_SMEM>>>(
            yh, dnh + (size_t)i * Hn * Dn, down_b + i * Hn,
            nullptr, nullptr, nullptr, hdnh, BLn, Hn, Dn);

        gemm_h<2><<<gpw, 256, GEMM_SMEM>>>(
            hdnh, uph + (size_t)i * Dn * Hn, up_b + i * Dn,
            y, nullptr, x, nullptr, BLn, Dn, Hn);
    }

    rmsnorm_k<<<BLn, 256>>>(x, fnw, nullptr, xnh);
    dim3 gl((Vn + 127) / 128, BLn / 128);  // (393, 32)
    gemm_h<0><<<gl, 256, GEMM_SMEM>>>(
        xnh, embh, nullptr, nullptr, nullptr, out, nullptr, BLn, Vn, Dn);
}

// round 14
// speedup vs baseline: 1.4738x; 1.0774x over previous
#include <cuda_runtime.h>
#include <cuda_fp16.h>
#include <cstdint>
#include <math.h>

#define Bn 2
#define Ln 2048
#define Dn 512
#define Vn 50257
#define NLn 12
#define Kn 5
#define An 128
#define Hn 128
#define BLn (Bn*Ln)
#define BLD (Bn*Ln*Dn)
#define CHK 128
#define CLEN 16
#define EGRIDC (BLD / 256)

#define SROW 36
#define SMEM_BM(BM)  (2 * ((BM) + 128) * SROW * 4)   /* 128:73728  64:55296 */
#define DUAL_SMEM    (2 * (64 + 256) * SROW * 4)     /* 92,160 (BM=64 dual) */

// ---------------- scratch (device globals) -----------------------------------
__device__ __align__(16) float  g_x[BLD];
__device__ __align__(16) float  g_xn[BLD];
__device__ __align__(16) float  g_y[BLD];
__device__ __align__(16) float  g_xs[Bn*Ln*An];
__device__ __align__(16) float  g_pc [Bn*CHK*An];
__device__ __align__(16) __half g_t1h[BLD];
__device__ __align__(16) __half g_yh[BLD];
__device__ __align__(16) __half g_hdnh[Bn*Ln*Hn];
__device__ __align__(16) __half g_xnh[BLD];
__device__ __align__(16) __half g_embh[Vn*Dn];
__device__ __align__(16) __half g_pwh [NLn*Dn*Dn];
__device__ __align__(16) __half g_w1h [NLn*Dn*Dn];
__device__ __align__(16) __half g_w2h [NLn*Dn*Dn];
__device__ __align__(16) __half g_dnh [NLn*Hn*Dn];
__device__ __align__(16) __half g_uph [NLn*Dn*Hn];

// ---------------- fp32 -> fp16 -----------------------------------------------
__global__ void f2h_k(const float* __restrict__ src, __half* __restrict__ dst,
                      int n4) {
    int i = blockIdx.x * blockDim.x + threadIdx.x;
    if (i >= n4) return;
    float4 v = ((const float4*)src)[i];
    ((__half2*)dst)[i * 2]     = __floats2half2_rn(v.x, v.y);
    ((__half2*)dst)[i * 2 + 1] = __floats2half2_rn(v.z, v.w);
}

// ---------------- embedding + rope ------------------------------------------
__global__ void embed_rope_k(const int* __restrict__ tok,
                             const float* __restrict__ emb,
                             float* __restrict__ x) {
    int idx = blockIdx.x * blockDim.x + threadIdx.x;
    if (idx >= BLD) return;
    int d  = idx & (Dn - 1);
    int bl = idx >> 9;
    int l  = bl & (Ln - 1);
    int t  = tok[bl];
    const float* e = emb + (size_t)t * Dn;
    const int half = Dn / 2;
    int fi = (d < half) ? d : d - half;
    float invf = powf(10000.f, -(float)fi / (float)half);
    float ang  = (float)l * invf;
    float s, c;
    sincosf(ang, &s, &c);
    float v = e[d];
    float partner = (d < half) ? -e[d + half] : e[d - half];
    x[idx] = v * c + partner * s;
}

// ---------------- rmsnorm ----------------------------------------------------
__global__ void rmsnorm_k(const float* __restrict__ x,
                          const float* __restrict__ w,
                          float* __restrict__ o,
                          __half* __restrict__ oh) {
    int row = blockIdx.x;
    int t = threadIdx.x;
    const float* xr = x + (size_t)row * Dn;
    float a  = xr[t];
    float b2 = xr[t + 256];
    __shared__ float red[256];
    red[t] = a * a + b2 * b2;
    __syncthreads();
    for (int s = 128; s > 0; s >>= 1) {
        if (t < s) red[t] += red[t + s];
        __syncthreads();
    }
    float scale = rsqrtf(red[0] / (float)Dn + 1e-6f);
    float v0 = w[t] * a * scale;
    float v1 = w[t + 256] * b2 * scale;
    if (o) {
        o[(size_t)row * Dn + t]       = v0;
        o[(size_t)row * Dn + t + 256] = v1;
    }
    if (oh) {
        oh[(size_t)row * Dn + t]       = __float2half_rn(v0);
        oh[(size_t)row * Dn + t + 256] = __float2half_rn(v1);
    }
}

// ---------------- fused dconv + recurrence chunk-sums ------------------------
__global__ void dconv_part_k(const float* __restrict__ xn,
                             const float* __restrict__ dw,
                             const float* __restrict__ db,
                             const float* __restrict__ alpha,
                             const float* __restrict__ beta,
                             __half* __restrict__ t1h,
                             float* __restrict__ pc,
                             int dil) {
    int bid = blockIdx.x;
    if (bid < EGRIDC) {
        int idx = bid * 256 + threadIdx.x;
        int d  = idx & (Dn - 1);
        int bl = idx >> 9;
        int l  = bl & (Ln - 1);
        int b  = bl >> 11;
        float s = db[d];
#pragma unroll
        for (int k = 0; k < Kn; k++) {
            int t = l + (k - 2) * dil;
            if (t >= 0 && t < Ln)
                s += dw[d * Kn + k] * xn[(((size_t)(b * Ln + t)) << 9) + d];
        }
        t1h[idx] = __float2half_rn(s);
    } else if (threadIdx.x < An) {
        int r  = bid - EGRIDC;
        int ch = r & (CHK - 1);
        int b  = r >> 7;
        int a  = threadIdx.x;
        float al = alpha[a], be = beta[a];
        const float* xp = xn + ((size_t)(b * Ln + ch * CLEN) << 9) + a;
        float h = 0.f;
#pragma unroll
        for (int i = 0; i < CLEN; i++) h = fmaf(al, h, be * xp[(size_t)i << 9]);
        pc[(b * CHK + ch) * An + a] = h;
    }
}

// ---------------- fused carry-recompute + apply ------------------------------
__global__ void scan_apply_k(const float* __restrict__ xn,
                             const float* __restrict__ alpha,
                             const float* __restrict__ beta,
                             const float* __restrict__ pc,
                             float* __restrict__ xs) {
    int ch = blockIdx.x & (CHK - 1);
    int b  = blockIdx.x >> 7;
    int a  = threadIdx.x;
    float al = alpha[a], be = beta[a];
    float f = al;
#pragma unroll
    for (int q = 0; q < 4; q++) f *= f;
    float h = 0.f;
    const float* pp = pc + (size_t)b * CHK * An + a;
    for (int c = 0; c < ch; c++)
        h = fmaf(f, h, pp[(size_t)c * An]);
    const float* xp = xn + ((size_t)(b * Ln + ch * CLEN) << 9) + a;
    float* op = xs + (size_t)(b * Ln + ch * CLEN) * An + a;
#pragma unroll
    for (int i = 0; i < CLEN; i++) {
        h = fmaf(al, h, be * xp[(size_t)i << 9]);
        op[i * An] = h;
    }
}

// ---------------- helpers ----------------------------------------------------
__device__ __forceinline__ void cp16(uint32_t dst, const void* src, bool pred) {
    asm volatile("cp.async.cg.shared.global [%0], [%1], 16, %2;\n"
                 :: "r"(dst), "l"(src), "r"(pred ? 16 : 0));
}
#define HMMA(acc, a, b)                                                        \
    asm volatile(                                                              \
        "mma.sync.aligned.m16n8k16.row.col.f32.f16.f16.f32 "                   \
        "{%0,%1,%2,%3}, {%4,%5,%6,%7}, {%8,%9}, {%0,%1,%2,%3};\n"              \
        : "+f"(acc[0]), "+f"(acc[1]), "+f"(acc[2]), "+f"(acc[3])               \
        : "r"(a[0]), "r"(a[1]), "r"(a[2]), "r"(a[3]), "r"(b[0]), "r"(b[1]))
#define LDSM4(r0, r1, r2, r3, addr)                                            \
    asm volatile("ldmatrix.sync.aligned.m8n8.x4.shared.b16 {%0,%1,%2,%3}, [%4];" \
                 : "=r"(r0), "=r"(r1), "=r"(r2), "=r"(r3) : "r"(addr))

// ---------------- fp16 GEMM, BMx128 tile, BK=64, 2-stage ---------------------
// BM=128: warp tile 64x32 (MT=4). BM=64: warp tile 32x32 (MT=2, 2x CTAs).
// EPI 0: C=v   EPI 1: gelu->Ch   EPI 2: C=C+add1+v
// EPI 3: C = v + (col<An ? add1[m*An+col] : aux[idx]);  Ch mirror
template <int EPI, int BM>
__global__ void __launch_bounds__(256)
gemm_h(const __half* __restrict__ A,
       const __half* __restrict__ Bw,
       const float* __restrict__ bias,
       const float* __restrict__ add1,
       const float* __restrict__ aux,
       float* __restrict__ C,
       __half* __restrict__ Ch,
       int M, int N, int K) {
    extern __shared__ uint32_t sm[];
    const uint32_t sbase = (uint32_t)__cvta_generic_to_shared(sm);
    const uint32_t bbase = sbase + 2 * BM * SROW * 4;
    constexpr int MT = BM / 32;                   // m-frags per warp

    const int tid  = threadIdx.x;
    const int m0   = blockIdx.y * BM;
    const int n0   = blockIdx.x * 128;
    const int wid  = tid >> 5;
    const int lane = tid & 31;
    const int gid  = lane >> 2;
    const int tig  = lane & 3;
    const int mb   = (wid >> 2) * (BM / 2);
    const int nb   = (wid & 3) * 32;

    const uint32_t aoff = (((uint32_t)(lane & 15)) * SROW + ((lane >> 4) & 1) * 4) * 4;
    const uint32_t boff = (((uint32_t)((lane & 7) + ((lane >> 4) & 1) * 8)) * SROW
                           + ((lane >> 3) & 1) * 4) * 4;

    float acc[MT][4][4];
#pragma unroll
    for (int mt = 0; mt < MT; mt++)
#pragma unroll
        for (int nt = 0; nt < 4; nt++)
#pragma unroll
            for (int r = 0; r < 4; r++) acc[mt][nt][r] = 0.f;

    const int KT = K >> 6;

    auto issue = [&](int kt, int s) {
        int k0 = kt << 6;
#pragma unroll
        for (int j = 0; j < BM / 32; j++) {       // A: BM rows
            int cid = tid + j * 256;
            int r   = cid >> 3;
            int col = cid & 7;
            cp16(sbase + ((s * BM + r) * SROW + col * 4) * 4,
                 A + (size_t)(m0 + r) * K + k0 + col * 8, true);
        }
#pragma unroll
        for (int j = 0; j < 4; j++) {             // B: 128 rows
            int cid = tid + j * 256;
            int r   = cid >> 3;
            int col = cid & 7;
            int nr  = n0 + r;
            cp16(bbase + ((s * 128 + r) * SROW + col * 4) * 4,
                 Bw + (size_t)(nr < N ? nr : 0) * K + k0 + col * 8, nr < N);
        }
    };

    issue(0, 0);
    asm volatile("cp.async.commit_group;\n");

    for (int kt = 0; kt < KT; kt++) {
        int s = kt & 1;
        if (kt + 1 < KT) {
            issue(kt + 1, s ^ 1);
            asm volatile("cp.async.commit_group;\n");
            asm volatile("cp.async.wait_group 1;\n");
        } else {
            asm volatile("cp.async.wait_group 0;\n");
        }
        __syncthreads();

        const uint32_t as0 = sbase + (uint32_t)(s * BM * SROW * 4) + aoff;
        const uint32_t bs0 = bbase + (uint32_t)(s * 128 * SROW * 4) + boff;
#pragma unroll
        for (int k8 = 0; k8 < 4; k8++) {
            const uint32_t ko4 = (uint32_t)(k8 * 8) * 4;
            uint32_t a[MT][4], b[4][2];
#pragma unroll
            for (int mt = 0; mt < MT; mt++)
                LDSM4(a[mt][0], a[mt][1], a[mt][2], a[mt][3],
                      as0 + (uint32_t)((mb + mt * 16) * SROW * 4) + ko4);
#pragma unroll
            for (int p = 0; p < 2; p++)
                LDSM4(b[2*p][0], b[2*p][1], b[2*p+1][0], b[2*p+1][1],
                      bs0 + (uint32_t)((nb + p * 16) * SROW * 4) + ko4);
#pragma unroll
            for (int mt = 0; mt < MT; mt++)
#pragma unroll
                for (int nt = 0; nt < 4; nt++)
                    HMMA(acc[mt][nt], a[mt], b[nt]);
        }
        __syncthreads();
    }

#pragma unroll
    for (int mt = 0; mt < MT; mt++) {
        int row0 = m0 + mb + mt * 16 + gid;
#pragma unroll
        for (int nt = 0; nt < 4; nt++) {
            int col0 = n0 + nb + nt * 8 + tig * 2;
#pragma unroll
            for (int hf = 0; hf < 2; hf++) {
                int rr = row0 + hf * 8;
#pragma unroll
                for (int cc = 0; cc < 2; cc++) {
                    int col = col0 + cc;
                    if (col < N) {
                        float v = acc[mt][nt][hf * 2 + cc] + (bias ? bias[col] : 0.f);
                        size_t idx = (size_t)rr * N + col;
                        if (EPI == 0) {
                            C[idx] = v;
                        } else if (EPI == 1) {
                            float g = 0.5f * v * (1.f + erff(v * 0.70710678118654752f));
                            Ch[idx] = __float2half_rn(g);
                        } else if (EPI == 2) {
                            C[idx] = C[idx] + add1[idx] + v;
                        } else {
                            float r = (col < An) ? add1[(size_t)rr * An + col]
                                                 : aux[idx];
                            float o = v + r;
                            C[idx]  = o;
                            Ch[idx] = __float2half_rn(o);
                        }
                    }
                }
            }
        }
    }
}

// ---------------- fused w1|w2 GEMM + GLU (BM=64, 2 CTA/SM) -------------------
__global__ void __launch_bounds__(256)
w1w2glu_k(const __half* __restrict__ Ah,
          const __half* __restrict__ W1,
          const __half* __restrict__ W2,
          const float* __restrict__ b1,
          const float* __restrict__ b2,
          float* __restrict__ y,
          __half* __restrict__ yh) {
    extern __shared__ uint32_t sm[];
    const uint32_t sbase  = (uint32_t)__cvta_generic_to_shared(sm);
    const uint32_t b1base = sbase + 2 * 64 * SROW * 4;
    const uint32_t b2base = b1base + 2 * 128 * SROW * 4;

    const int tid  = threadIdx.x;
    const int m0   = blockIdx.y * 64;
    const int n0   = blockIdx.x * 128;
    const int wid  = tid >> 5;
    const int lane = tid & 31;
    const int gid  = lane >> 2;
    const int tig  = lane & 3;
    const int mb   = (wid >> 2) * 32;
    const int nb   = (wid & 3) * 32;
    const int K    = Dn;

    const uint32_t aoff = (((uint32_t)(lane & 15)) * SROW + ((lane >> 4) & 1) * 4) * 4;
    const uint32_t boff = (((uint32_t)((lane & 7) + ((lane >> 4) & 1) * 8)) * SROW
                           + ((lane >> 3) & 1) * 4) * 4;

    float acc1[2][4][4], acc2[2][4][4];
#pragma unroll
    for (int mt = 0; mt < 2; mt++)
#pragma unroll
        for (int nt = 0; nt < 4; nt++)
#pragma unroll
            for (int r = 0; r < 4; r++) { acc1[mt][nt][r] = 0.f; acc2[mt][nt][r] = 0.f; }

    const int KT = K >> 6;

    auto issue = [&](int kt, int s) {
        int k0 = kt << 6;
#pragma unroll
        for (int j = 0; j < 2; j++) {             // A: 64 rows
            int cid = tid + j * 256;
            int r   = cid >> 3;
            int col = cid & 7;
            cp16(sbase + ((s * 64 + r) * SROW + col * 4) * 4,
                 Ah + (size_t)(m0 + r) * K + k0 + col * 8, true);
        }
#pragma unroll
        for (int j = 0; j < 4; j++) {             // B1/B2: 128 rows each
            int cid = tid + j * 256;
            int r   = cid >> 3;
            int col = cid & 7;
            uint32_t so = ((s * 128 + r) * SROW + col * 4) * 4;
            cp16(b1base + so, W1 + (size_t)(n0 + r) * K + k0 + col * 8, true);
            cp16(b2base + so, W2 + (size_t)(n0 + r) * K + k0 + col * 8, true);
        }
    };

    issue(0, 0);
    asm volatile("cp.async.commit_group;\n");

    for (int kt = 0; kt < KT; kt++) {
        int s = kt & 1;
        if (kt + 1 < KT) {
            issue(kt + 1, s ^ 1);
            asm volatile("cp.async.commit_group;\n");
            asm volatile("cp.async.wait_group 1;\n");
        } else {
            asm volatile("cp.async.wait_group 0;\n");
        }
        __syncthreads();

        const uint32_t as0  = sbase  + (uint32_t)(s * 64 * SROW * 4) + aoff;
        const uint32_t b1s0 = b1base + (uint32_t)(s * 128 * SROW * 4) + boff;
        const uint32_t b2s0 = b2base + (uint32_t)(s * 128 * SROW * 4) + boff;
#pragma unroll
        for (int k8 = 0; k8 < 4; k8++) {
            const uint32_t ko4 = (uint32_t)(k8 * 8) * 4;
            uint32_t a[2][4], br1[4][2], br2[4][2];
#pragma unroll
            for (int mt = 0; mt < 2; mt++)
                LDSM4(a[mt][0], a[mt][1], a[mt][2], a[mt][3],
                      as0 + (uint32_t)((mb + mt * 16) * SROW * 4) + ko4);
#pragma unroll
            for (int p = 0; p < 2; p++) {
                LDSM4(br1[2*p][0], br1[2*p][1], br1[2*p+1][0], br1[2*p+1][1],
                      b1s0 + (uint32_t)((nb + p * 16) * SROW * 4) + ko4);
                LDSM4(br2[2*p][0], br2[2*p][1], br2[2*p+1][0], br2[2*p+1][1],
                      b2s0 + (uint32_t)((nb + p * 16) * SROW * 4) + ko4);
            }
#pragma unroll
            for (int mt = 0; mt < 2; mt++)
#pragma unroll
                for (int nt = 0; nt < 4; nt++) {
                    HMMA(acc1[mt][nt], a[mt], br1[nt]);
                    HMMA(acc2[mt][nt], a[mt], br2[nt]);
                }
        }
        __syncthreads();
    }

#pragma unroll
    for (int mt = 0; mt < 2; mt++) {
        int row0 = m0 + mb + mt * 16 + gid;
#pragma unroll
        for (int nt = 0; nt < 4; nt++) {
            int col0 = n0 + nb + nt * 8 + tig * 2;
#pragma unroll
            for (int hf = 0; hf < 2; hf++) {
                int rr = row0 + hf * 8;
#pragma unroll
                for (int cc = 0; cc < 2; cc++) {
                    int col = col0 + cc;
                    float v1 = acc1[mt][nt][hf * 2 + cc] + b1[col];
                    float v2 = acc2[mt][nt][hf * 2 + cc] + b2[col];
                    size_t idx = (size_t)rr * Dn + col;
                    float o = y[idx] + (1.f / (1.f + expf(-v1))) * tanhf(v2);
                    y[idx]  = o;
                    yh[idx] = __float2half_rn(o);
                }
            }
        }
    }
}

// ---------------- host ------------------------------------------------------
extern "C" void kernel_launch(void* const* d_in, const int* in_sizes, int n_in,
                              void* d_out, int out_size) {
    const int*   tokens  = (const int*)  d_in[0];
    const float* emb     = (const float*)d_in[1];
    const float* norm_w  = (const float*)d_in[2];
    const float* dconv_w = (const float*)d_in[3];
    const float* dconv_b = (const float*)d_in[4];
    const float* pconv_w = (const float*)d_in[5];
    const float* pconv_b = (const float*)d_in[6];
    const float* alpha   = (const float*)d_in[7];
    const float* beta    = (const float*)d_in[8];
    const float* w1      = (const float*)d_in[9];
    const float* b1      = (const float*)d_in[10];
    const float* w2      = (const float*)d_in[11];
    const float* b2      = (const float*)d_in[12];
    const float* down_w  = (const float*)d_in[13];
    const float* down_b  = (const float*)d_in[14];
    const float* up_w    = (const float*)d_in[15];
    const float* up_b    = (const float*)d_in[16];
    const float* fnw     = (const float*)d_in[17];
    float* out = (float*)d_out;

    float *x, *xn, *y, *xs, *pc;
    __half *t1h, *yh, *hdnh, *xnh, *embh, *pwh, *w1h, *w2h, *dnh, *uph;
    cudaGetSymbolAddress((void**)&x,    g_x);
    cudaGetSymbolAddress((void**)&xn,   g_xn);
    cudaGetSymbolAddress((void**)&y,    g_y);
    cudaGetSymbolAddress((void**)&xs,   g_xs);
    cudaGetSymbolAddress((void**)&pc,   g_pc);
    cudaGetSymbolAddress((void**)&t1h,  g_t1h);
    cudaGetSymbolAddress((void**)&yh,   g_yh);
    cudaGetSymbolAddress((void**)&hdnh, g_hdnh);
    cudaGetSymbolAddress((void**)&xnh,  g_xnh);
    cudaGetSymbolAddress((void**)&embh, g_embh);
    cudaGetSymbolAddress((void**)&pwh,  g_pwh);
    cudaGetSymbolAddress((void**)&w1h,  g_w1h);
    cudaGetSymbolAddress((void**)&w2h,  g_w2h);
    cudaGetSymbolAddress((void**)&dnh,  g_dnh);
    cudaGetSymbolAddress((void**)&uph,  g_uph);

    cudaFuncSetAttribute(gemm_h<0,128>, cudaFuncAttributeMaxDynamicSharedMemorySize, SMEM_BM(128));
    cudaFuncSetAttribute(gemm_h<1,64>,  cudaFuncAttributeMaxDynamicSharedMemorySize, SMEM_BM(64));
    cudaFuncSetAttribute(gemm_h<2,64>,  cudaFuncAttributeMaxDynamicSharedMemorySize, SMEM_BM(64));
    cudaFuncSetAttribute(gemm_h<3,64>,  cudaFuncAttributeMaxDynamicSharedMemorySize, SMEM_BM(64));
    cudaFuncSetAttribute(w1w2glu_k,     cudaFuncAttributeMaxDynamicSharedMemorySize, DUAL_SMEM);

    {
        int n;
        n = Vn * Dn / 4;        f2h_k<<<(n + 255) / 256, 256>>>(emb,     embh, n);
        n = NLn * Dn * Dn / 4;  f2h_k<<<(n + 255) / 256, 256>>>(pconv_w, pwh,  n);
        n = NLn * Dn * Dn / 4;  f2h_k<<<(n + 255) / 256, 256>>>(w1,      w1h,  n);
        n = NLn * Dn * Dn / 4;  f2h_k<<<(n + 255) / 256, 256>>>(w2,      w2h,  n);
        n = NLn * Hn * Dn / 4;  f2h_k<<<(n + 255) / 256, 256>>>(down_w,  dnh,  n);
        n = NLn * Dn * Hn / 4;  f2h_k<<<(n + 255) / 256, 256>>>(up_w,    uph,  n);
    }

    embed_rope_k<<<EGRIDC, 256>>>(tokens, emb, x);

    for (int i = 0; i < NLn; i++) {
        int dil = 1 << (i % 3);
        rmsnorm_k<<<BLn, 256>>>(x, norm_w + i * Dn, xn, nullptr);
        dconv_part_k<<<EGRIDC + Bn * CHK, 256>>>(
            xn, dconv_w + (size_t)i * Dn * Kn, dconv_b + i * Dn,
            alpha + i * An, beta + i * An, t1h, pc, dil);
        scan_apply_k<<<Bn * CHK, An>>>(xn, alpha + i * An, beta + i * An,
                                       pc, xs);

        dim3 g64(Dn / 128, BLn / 64);   // (4, 64) = 256 CTAs
        gemm_h<3,64><<<g64, 256, SMEM_BM(64)>>>(
            t1h, pwh + (size_t)i * Dn * Dn, pconv_b + i * Dn,
            xs, xn, y, yh, BLn, Dn, Dn);

        w1w2glu_k<<<g64, 256, DUAL_SMEM>>>(
            yh, w1h + (size_t)i * Dn * Dn, w2h + (size_t)i * Dn * Dn,
            b1 + i * Dn, b2 + i * Dn, y, yh);

        dim3 gdn(Hn / 128, BLn / 64);   // (1, 64) = 64 CTAs
        gemm_h<1,64><<<gdn, 256, SMEM_BM(64)>>>(
            yh, dnh + (size_t)i * Hn * Dn, down_b + i * Hn,
            nullptr, nullptr, nullptr, hdnh, BLn, Hn, Dn);

        gemm_h<2,64><<<g64, 256, SMEM_BM(64)>>>(
            hdnh, uph + (size_t)i * Dn * Hn, up_b + i * Dn,
            y, nullptr, x, nullptr, BLn, Dn, Hn);
    }

    rmsnorm_k<<<BLn, 256>>>(x, fnw, nullptr, xnh);
    dim3 gl((Vn + 127) / 128, BLn / 128);  // (393, 32) — proven 128x128
    gemm_h<0,128><<<gl, 256, SMEM_BM(128)>>>(
        xnh, embh, nullptr, nullptr, nullptr, out, nullptr, BLn, Vn, Dn);
}